// round 2
// baseline (speedup 1.0000x reference)
#include <cuda_runtime.h>
#include <math.h>

// VolatilityLoss: mean((std3(pred) - std3(targ))^2) over sliding windows of 3.
// B=512, S=8192, L=8190 outputs/row.

#define B_ROWS 512
#define S_LEN  8192
#define L_OUT  (S_LEN - 2)          // 8190
#define GROUPS_PER_ROW 2048         // ceil(8190/4)
#define TOTAL_GROUPS (B_ROWS * GROUPS_PER_ROW)
#define NBLOCKS 2048
#define NTHREADS 256

__device__ float g_partials[NBLOCKS];

__device__ __forceinline__ float std3(float a, float b, float c) {
    float m  = (a + b + c) * (1.0f / 3.0f);
    float da = a - m, db = b - m, dc = c - m;
    float var = (da * da + db * db + dc * dc) * 0.5f;
    return sqrtf(var);   // sum of squares => var >= 0
}

__global__ void __launch_bounds__(NTHREADS)
vol_loss_main(const float* __restrict__ pred, const float* __restrict__ targ) {
    float acc = 0.0f;

    for (int g = blockIdx.x * NTHREADS + threadIdx.x; g < TOTAL_GROUPS;
         g += gridDim.x * NTHREADS) {
        int row   = g >> 11;          // g / GROUPS_PER_ROW
        int start = (g & 2047) << 2;  // (g % GROUPS_PER_ROW) * 4

        const float4* p4 = (const float4*)(pred + (size_t)row * S_LEN + start);
        const float4* t4 = (const float4*)(targ + (size_t)row * S_LEN + start);

        float4 p0 = p4[0];
        float4 t0 = t4[0];
        float4 p1 = make_float4(0.f, 0.f, 0.f, 0.f);
        float4 t1 = make_float4(0.f, 0.f, 0.f, 0.f);
        // Second vector would cross the row boundary only for the last group
        // (start = 8188); its valid windows use only the first float4.
        if (start + 4 < S_LEN) {
            p1 = p4[1];
            t1 = t4[1];
        }

        float pe[8] = {p0.x, p0.y, p0.z, p0.w, p1.x, p1.y, p1.z, p1.w};
        float te[8] = {t0.x, t0.y, t0.z, t0.w, t1.x, t1.y, t1.z, t1.w};

        #pragma unroll
        for (int j = 0; j < 4; ++j) {
            if (start + j < L_OUT) {
                float d = std3(pe[j], pe[j + 1], pe[j + 2])
                        - std3(te[j], te[j + 1], te[j + 2]);
                acc = fmaf(d, d, acc);
            }
        }
    }

    // Deterministic block reduction: warp shuffle tree + shared.
    #pragma unroll
    for (int o = 16; o > 0; o >>= 1)
        acc += __shfl_down_sync(0xffffffffu, acc, o);

    __shared__ float red[NTHREADS / 32];
    int lane = threadIdx.x & 31;
    int warp = threadIdx.x >> 5;
    if (lane == 0) red[warp] = acc;
    __syncthreads();

    if (warp == 0) {
        float v = (lane < NTHREADS / 32) ? red[lane] : 0.0f;
        #pragma unroll
        for (int o = 4; o > 0; o >>= 1)
            v += __shfl_down_sync(0xffffffffu, v, o);
        if (lane == 0) g_partials[blockIdx.x] = v;
    }
}

__global__ void __launch_bounds__(256)
vol_loss_finalize(float* __restrict__ out) {
    __shared__ double sh[256];
    double s = 0.0;
    for (int i = threadIdx.x; i < NBLOCKS; i += 256)
        s += (double)g_partials[i];
    sh[threadIdx.x] = s;
    __syncthreads();
    #pragma unroll
    for (int stride = 128; stride > 0; stride >>= 1) {
        if (threadIdx.x < stride) sh[threadIdx.x] += sh[threadIdx.x + stride];
        __syncthreads();
    }
    if (threadIdx.x == 0)
        out[0] = (float)(sh[0] / ((double)B_ROWS * (double)L_OUT));
}

extern "C" void kernel_launch(void* const* d_in, const int* in_sizes, int n_in,
                              void* d_out, int out_size) {
    const float* pred = (const float*)d_in[0];
    const float* targ = (const float*)d_in[1];
    float* out = (float*)d_out;

    vol_loss_main<<<NBLOCKS, NTHREADS>>>(pred, targ);
    vol_loss_finalize<<<1, 256>>>(out);
}

// round 3
// speedup vs baseline: 1.1356x; 1.1356x over previous
#include <cuda_runtime.h>
#include <math.h>

// VolatilityLoss: mean((std3(pred) - std3(targ))^2), sliding window w=3.
// B=512, S=8192, L=8190 outputs/row. Single fused kernel:
// grid-wide partials + fence/atomic "last block" final reduction.

#define B_ROWS 512
#define S_LEN  8192
#define L_OUT  (S_LEN - 2)          // 8190
#define GROUPS_PER_ROW 1024         // 8 outputs per group
#define NBLOCKS 2048
#define NTHREADS 256
// NBLOCKS*NTHREADS == B_ROWS*GROUPS_PER_ROW exactly (one group per thread)

__device__ float        g_partials[NBLOCKS];
__device__ unsigned int g_counter = 0;   // monotone across graph replays

__device__ __forceinline__ float sqrt_approx(float x) {
    float r;
    asm("sqrt.approx.f32 %0, %1;" : "=f"(r) : "f"(x));
    return r;
}

__device__ __forceinline__ float std3(float a, float b, float c) {
    float m  = (a + b + c) * (1.0f / 3.0f);
    float da = a - m, db = b - m, dc = c - m;
    float var = fmaf(da, da, fmaf(db, db, dc * dc)) * 0.5f;
    return sqrt_approx(var);   // var >= 0 by construction
}

__global__ void __launch_bounds__(NTHREADS)
vol_loss_fused(const float* __restrict__ pred, const float* __restrict__ targ,
               float* __restrict__ out) {
    int g     = blockIdx.x * NTHREADS + threadIdx.x;
    int row   = g >> 10;             // g / GROUPS_PER_ROW
    int start = (g & 1023) << 3;     // 8 outputs starting here

    const float4* p4 = (const float4*)(pred + (size_t)row * S_LEN + start);
    const float4* t4 = (const float4*)(targ + (size_t)row * S_LEN + start);

    // Front-batched loads: 6x LDG.128 (MLP=6). Third vector crosses the row
    // boundary only for the last group of a row (start=8184), whose valid
    // windows need only elements start..start+7.
    float4 p0 = p4[0], p1 = p4[1];
    float4 t0 = t4[0], t1 = t4[1];
    float4 p2 = make_float4(0.f, 0.f, 0.f, 0.f);
    float4 t2 = make_float4(0.f, 0.f, 0.f, 0.f);
    if (start + 12 <= S_LEN) { p2 = p4[2]; t2 = t4[2]; }

    float pe[12] = {p0.x, p0.y, p0.z, p0.w, p1.x, p1.y, p1.z, p1.w,
                    p2.x, p2.y, p2.z, p2.w};
    float te[12] = {t0.x, t0.y, t0.z, t0.w, t1.x, t1.y, t1.z, t1.w,
                    t2.x, t2.y, t2.z, t2.w};

    float acc = 0.0f;
    #pragma unroll
    for (int j = 0; j < 8; ++j) {
        if (start + j < L_OUT) {
            float d = std3(pe[j], pe[j + 1], pe[j + 2])
                    - std3(te[j], te[j + 1], te[j + 2]);
            acc = fmaf(d, d, acc);
        }
    }

    // Deterministic intra-block reduction.
    #pragma unroll
    for (int o = 16; o > 0; o >>= 1)
        acc += __shfl_down_sync(0xffffffffu, acc, o);

    __shared__ float red[NTHREADS / 32];
    int lane = threadIdx.x & 31;
    int warp = threadIdx.x >> 5;
    if (lane == 0) red[warp] = acc;
    __syncthreads();

    __shared__ bool is_last;
    if (threadIdx.x == 0) {
        float v = 0.0f;
        #pragma unroll
        for (int w = 0; w < NTHREADS / 32; ++w) v += red[w];
        g_partials[blockIdx.x] = v;
        __threadfence();
        unsigned int old = atomicAdd(&g_counter, 1u);
        is_last = ((old + 1u) % (unsigned)NBLOCKS) == 0u;
    }
    __syncthreads();

    if (!is_last) return;

    // Last-arriving block: deterministic final reduction over 2048 partials
    // (all visible: every writer fenced before its atomic arrival).
    __shared__ double sh[NTHREADS];
    double s = 0.0;
    for (int i = threadIdx.x; i < NBLOCKS; i += NTHREADS)
        s += (double)g_partials[i];
    sh[threadIdx.x] = s;
    __syncthreads();
    #pragma unroll
    for (int stride = NTHREADS / 2; stride > 0; stride >>= 1) {
        if (threadIdx.x < stride) sh[threadIdx.x] += sh[threadIdx.x + stride];
        __syncthreads();
    }
    if (threadIdx.x == 0)
        out[0] = (float)(sh[0] / ((double)B_ROWS * (double)L_OUT));
}

extern "C" void kernel_launch(void* const* d_in, const int* in_sizes, int n_in,
                              void* d_out, int out_size) {
    const float* pred = (const float*)d_in[0];
    const float* targ = (const float*)d_in[1];
    vol_loss_fused<<<NBLOCKS, NTHREADS>>>(pred, targ, (float*)d_out);
}